// round 1
// baseline (speedup 1.0000x reference)
#include <cuda_runtime.h>
#include <math.h>
#include <stdint.h>

// Problem constants
#define BATCH 16384
#define DIM   1024
#define DIM2  2048

// ---------------- scratch (static device globals; no allocs) ----------------
__device__ float g_z[(size_t)BATCH * DIM2];   // 128 MB: concat(z1, z2), LN'd in place
__device__ float g_B1[DIM * DIM];             // combined weight path 1: B1[k][n]
__device__ float g_B2[DIM * DIM];             // combined weight path 2
__device__ float g_c1[DIM];                   // combined bias path 1
__device__ float g_c2[DIM];                   // combined bias path 2

// ---------------- generic fp32 GEMM ----------------
// C[m,n] = sum_k Xeff[m,k] * Beff[k,n] + bias[n]   (optional exact-erf GELU)
//   XT=false: Xeff[m,k] = X[m*lda + k]   (row-major [M,K])
//   XT=true : Xeff[m,k] = X[k*lda + m]   (row-major [K,M])
//   BT=false: Beff[k,n] = B[k*ldb + n]   (row-major [K,N])
//   BT=true : Beff[k,n] = B[n*ldb + k]   (row-major [N,K])
// Tile: 128x128x16, 256 threads, 8x8 per-thread, double-buffered smem.
// All dims assumed divisible by tile sizes (true here: 16384/1024/2048).
#define TILE  128
#define KTILE 16

template <bool XT, bool BT, bool GELU_EP>
__global__ __launch_bounds__(256, 2)
void gemm_kernel(const float* __restrict__ X, int lda,
                 const float* __restrict__ B, int ldb,
                 float* __restrict__ C, int ldc,
                 const float* __restrict__ bias,
                 int M, int N, int K)
{
    __shared__ float As[2][KTILE][TILE];
    __shared__ float Bs[2][KTILE][TILE];

    const int tid = threadIdx.x;
    const int tx = tid & 15;        // 0..15 -> column groups
    const int ty = tid >> 4;        // 0..15 -> row groups
    const int m0 = blockIdx.y * TILE;
    const int n0 = blockIdx.x * TILE;

    float acc[8][8];
#pragma unroll
    for (int i = 0; i < 8; i++)
#pragma unroll
        for (int j = 0; j < 8; j++) acc[i][j] = 0.0f;

    // per-thread load coordinates
    const int rT = tid >> 2;              // 0..63  (transpose-style loads, 16 wide in k)
    const int cT = (tid & 3) << 2;        // 0,4,8,12
    const int rD = tid >> 5;              // 0..7   (direct-style loads, 128 wide)
    const int cD = (tid & 31) << 2;       // 0..124

    float4 pA0, pA1, pB0, pB1;

    // ---- fetch tile (global -> registers) ----
    auto fetch = [&](int k0) {
        if (!XT) {
            pA0 = *reinterpret_cast<const float4*>(&X[(size_t)(m0 + rT) * lda + k0 + cT]);
            pA1 = *reinterpret_cast<const float4*>(&X[(size_t)(m0 + rT + 64) * lda + k0 + cT]);
        } else {
            pA0 = *reinterpret_cast<const float4*>(&X[(size_t)(k0 + rD) * lda + m0 + cD]);
            pA1 = *reinterpret_cast<const float4*>(&X[(size_t)(k0 + rD + 8) * lda + m0 + cD]);
        }
        if (!BT) {
            pB0 = *reinterpret_cast<const float4*>(&B[(size_t)(k0 + rD) * ldb + n0 + cD]);
            pB1 = *reinterpret_cast<const float4*>(&B[(size_t)(k0 + rD + 8) * ldb + n0 + cD]);
        } else {
            pB0 = *reinterpret_cast<const float4*>(&B[(size_t)(n0 + rT) * ldb + k0 + cT]);
            pB1 = *reinterpret_cast<const float4*>(&B[(size_t)(n0 + rT + 64) * ldb + k0 + cT]);
        }
    };

    // ---- store tile (registers -> smem) ----
    auto store = [&](int buf) {
        if (!XT) {
            As[buf][cT + 0][rT] = pA0.x; As[buf][cT + 1][rT] = pA0.y;
            As[buf][cT + 2][rT] = pA0.z; As[buf][cT + 3][rT] = pA0.w;
            As[buf][cT + 0][rT + 64] = pA1.x; As[buf][cT + 1][rT + 64] = pA1.y;
            As[buf][cT + 2][rT + 64] = pA1.z; As[buf][cT + 3][rT + 64] = pA1.w;
        } else {
            *reinterpret_cast<float4*>(&As[buf][rD][cD]) = pA0;
            *reinterpret_cast<float4*>(&As[buf][rD + 8][cD]) = pA1;
        }
        if (!BT) {
            *reinterpret_cast<float4*>(&Bs[buf][rD][cD]) = pB0;
            *reinterpret_cast<float4*>(&Bs[buf][rD + 8][cD]) = pB1;
        } else {
            Bs[buf][cT + 0][rT] = pB0.x; Bs[buf][cT + 1][rT] = pB0.y;
            Bs[buf][cT + 2][rT] = pB0.z; Bs[buf][cT + 3][rT] = pB0.w;
            Bs[buf][cT + 0][rT + 64] = pB1.x; Bs[buf][cT + 1][rT + 64] = pB1.y;
            Bs[buf][cT + 2][rT + 64] = pB1.z; Bs[buf][cT + 3][rT + 64] = pB1.w;
        }
    };

    const int nk = K / KTILE;
    fetch(0);
    store(0);
    __syncthreads();

    for (int kb = 0; kb < nk; kb++) {
        const int cur = kb & 1;
        const bool more = (kb + 1 < nk);
        if (more) fetch((kb + 1) * KTILE);   // LDG overlaps compute below

#pragma unroll
        for (int kt = 0; kt < KTILE; kt++) {
            float a[8], b[8];
            *reinterpret_cast<float4*>(&a[0]) = *reinterpret_cast<const float4*>(&As[cur][kt][ty * 4]);
            *reinterpret_cast<float4*>(&a[4]) = *reinterpret_cast<const float4*>(&As[cur][kt][64 + ty * 4]);
            *reinterpret_cast<float4*>(&b[0]) = *reinterpret_cast<const float4*>(&Bs[cur][kt][tx * 4]);
            *reinterpret_cast<float4*>(&b[4]) = *reinterpret_cast<const float4*>(&Bs[cur][kt][64 + tx * 4]);
#pragma unroll
            for (int i = 0; i < 8; i++)
#pragma unroll
                for (int j = 0; j < 8; j++) acc[i][j] += a[i] * b[j];
        }

        if (more) store(cur ^ 1);
        __syncthreads();
    }

    // ---- epilogue ----
    float bcol[8];
#pragma unroll
    for (int jh = 0; jh < 2; jh++) {
        const int col = n0 + jh * 64 + tx * 4;
        if (bias) {
            float4 bv = *reinterpret_cast<const float4*>(&bias[col]);
            bcol[jh * 4 + 0] = bv.x; bcol[jh * 4 + 1] = bv.y;
            bcol[jh * 4 + 2] = bv.z; bcol[jh * 4 + 3] = bv.w;
        } else {
            bcol[jh * 4 + 0] = bcol[jh * 4 + 1] = bcol[jh * 4 + 2] = bcol[jh * 4 + 3] = 0.0f;
        }
    }

#pragma unroll
    for (int i = 0; i < 8; i++) {
        const int row = m0 + ((i < 4) ? (ty * 4 + i) : (64 + ty * 4 + (i - 4)));
#pragma unroll
        for (int jh = 0; jh < 2; jh++) {
            const int col = n0 + jh * 64 + tx * 4;
            float4 v;
            float* pv = &v.x;
#pragma unroll
            for (int q = 0; q < 4; q++) {
                float t = acc[i][jh * 4 + q] + bcol[jh * 4 + q];
                if (GELU_EP) t = 0.5f * t * (1.0f + erff(t * 0.70710678118654752f));
                pv[q] = t;
            }
            *reinterpret_cast<float4*>(&C[(size_t)row * ldc + col]) = v;
        }
    }
}

// ---------------- combined bias: c[n] = sum_j wo[n,j]*bv[j] + bo[n] ----------------
__global__ void biasc_kernel(const float* __restrict__ wo,
                             const float* __restrict__ bv,
                             const float* __restrict__ bo,
                             float* __restrict__ c)
{
    __shared__ float red[4];
    const int n = blockIdx.x;
    const int tid = threadIdx.x;  // 128
    float s = 0.0f;
    for (int j = tid; j < DIM; j += 128) s += wo[(size_t)n * DIM + j] * bv[j];
#pragma unroll
    for (int o = 16; o > 0; o >>= 1) s += __shfl_xor_sync(0xFFFFFFFFu, s, o);
    if ((tid & 31) == 0) red[tid >> 5] = s;
    __syncthreads();
    if (tid == 0) c[n] = red[0] + red[1] + red[2] + red[3] + bo[n];
}

// ---------------- in-place row LayerNorm over 2048 cols ----------------
__global__ void ln_kernel(float* __restrict__ z,
                          const float* __restrict__ g,
                          const float* __restrict__ b)
{
    __shared__ float redS[8], redQ[8];
    const size_t base = (size_t)blockIdx.x * DIM2;
    const int tid = threadIdx.x;  // 256

    float4 v0 = *reinterpret_cast<const float4*>(&z[base + tid * 4]);
    float4 v1 = *reinterpret_cast<const float4*>(&z[base + 1024 + tid * 4]);

    float s = v0.x + v0.y + v0.z + v0.w + v1.x + v1.y + v1.z + v1.w;
    float q = v0.x * v0.x + v0.y * v0.y + v0.z * v0.z + v0.w * v0.w
            + v1.x * v1.x + v1.y * v1.y + v1.z * v1.z + v1.w * v1.w;
#pragma unroll
    for (int o = 16; o > 0; o >>= 1) {
        s += __shfl_xor_sync(0xFFFFFFFFu, s, o);
        q += __shfl_xor_sync(0xFFFFFFFFu, q, o);
    }
    if ((tid & 31) == 0) { redS[tid >> 5] = s; redQ[tid >> 5] = q; }
    __syncthreads();
    float S = 0.0f, Q = 0.0f;
#pragma unroll
    for (int w = 0; w < 8; w++) { S += redS[w]; Q += redQ[w]; }

    const float mu = S * (1.0f / DIM2);
    const float var = Q * (1.0f / DIM2) - mu * mu;
    const float rstd = rsqrtf(var + 1e-5f);

    float4 g0 = *reinterpret_cast<const float4*>(&g[tid * 4]);
    float4 g1 = *reinterpret_cast<const float4*>(&g[1024 + tid * 4]);
    float4 b0 = *reinterpret_cast<const float4*>(&b[tid * 4]);
    float4 b1 = *reinterpret_cast<const float4*>(&b[1024 + tid * 4]);

    v0.x = (v0.x - mu) * rstd * g0.x + b0.x;
    v0.y = (v0.y - mu) * rstd * g0.y + b0.y;
    v0.z = (v0.z - mu) * rstd * g0.z + b0.z;
    v0.w = (v0.w - mu) * rstd * g0.w + b0.w;
    v1.x = (v1.x - mu) * rstd * g1.x + b1.x;
    v1.y = (v1.y - mu) * rstd * g1.y + b1.y;
    v1.z = (v1.z - mu) * rstd * g1.z + b1.z;
    v1.w = (v1.w - mu) * rstd * g1.w + b1.w;

    *reinterpret_cast<float4*>(&z[base + tid * 4]) = v0;
    *reinterpret_cast<float4*>(&z[base + 1024 + tid * 4]) = v1;
}

// ---------------- launch ----------------
extern "C" void kernel_launch(void* const* d_in, const int* in_sizes, int n_in,
                              void* d_out, int out_size)
{
    const float* x_u    = (const float*)d_in[0];
    const float* x_m    = (const float*)d_in[1];
    const float* w_qkv1 = (const float*)d_in[2];
    const float* b_qkv1 = (const float*)d_in[3];
    const float* w_o1   = (const float*)d_in[4];
    const float* b_o1   = (const float*)d_in[5];
    const float* w_qkv2 = (const float*)d_in[6];
    const float* b_qkv2 = (const float*)d_in[7];
    const float* w_o2   = (const float*)d_in[8];
    const float* b_o2   = (const float*)d_in[9];
    const float* ln_g   = (const float*)d_in[10];
    const float* ln_b   = (const float*)d_in[11];
    const float* w_proj = (const float*)d_in[12];
    const float* b_proj = (const float*)d_in[13];
    float* out = (float*)d_out;

    const float* wv1 = w_qkv1 + (size_t)2 * DIM * DIM;  // V-projection rows
    const float* bv1 = b_qkv1 + 2 * DIM;
    const float* wv2 = w_qkv2 + (size_t)2 * DIM * DIM;
    const float* bv2 = b_qkv2 + 2 * DIM;

    float *z, *B1, *B2, *c1, *c2;
    cudaGetSymbolAddress((void**)&z,  g_z);
    cudaGetSymbolAddress((void**)&B1, g_B1);
    cudaGetSymbolAddress((void**)&B2, g_B2);
    cudaGetSymbolAddress((void**)&c1, g_c1);
    cudaGetSymbolAddress((void**)&c2, g_c2);

    // 1) combine weights: Bp[k,n] = sum_j wv[j,k] * wo[n,j]   (XT=true, BT=true)
    dim3 gridW(DIM / TILE, DIM / TILE);           // 8x8
    gemm_kernel<true, true, false><<<gridW, 256>>>(wv1, DIM, w_o1, DIM, B1, DIM, nullptr, DIM, DIM, DIM);
    gemm_kernel<true, true, false><<<gridW, 256>>>(wv2, DIM, w_o2, DIM, B2, DIM, nullptr, DIM, DIM, DIM);

    // 2) combine biases
    biasc_kernel<<<DIM, 128>>>(w_o1, bv1, b_o1, c1);
    biasc_kernel<<<DIM, 128>>>(w_o2, bv2, b_o2, c2);

    // 3) z1 = x_u @ B1 + c1 -> z[:, :1024]; z2 = x_m @ B2 + c2 -> z[:, 1024:]
    dim3 gridZ(DIM / TILE, BATCH / TILE);         // 8x128
    gemm_kernel<false, false, false><<<gridZ, 256>>>(x_u, DIM, B1, DIM, z, DIM2, c1, BATCH, DIM, DIM);
    gemm_kernel<false, false, false><<<gridZ, 256>>>(x_m, DIM, B2, DIM, z + DIM, DIM2, c2, BATCH, DIM, DIM);

    // 4) LayerNorm in place over 2048 cols
    ln_kernel<<<BATCH, 256>>>(z, ln_g, ln_b);

    // 5) out = GELU(zn @ w_proj^T + b_proj)   (BT=true: Beff[k,n] = w_proj[n*2048+k])
    dim3 gridP(DIM / TILE, BATCH / TILE);         // 8x128
    gemm_kernel<false, true, true><<<gridP, 256>>>(z, DIM2, w_proj, DIM2, out, DIM, b_proj, BATCH, DIM, DIM2);
}

// round 4
// speedup vs baseline: 2.2126x; 2.2126x over previous
#include <cuda_runtime.h>
#include <cuda_bf16.h>
#include <math.h>
#include <stdint.h>

#define BATCH 16384
#define DIM   1024
#define DIM2  2048

// ---------------- scratch (device globals; no allocs) ----------------
__device__ __nv_bfloat16 g_xu_hi[(size_t)BATCH*DIM], g_xu_lo[(size_t)BATCH*DIM];
__device__ __nv_bfloat16 g_xm_hi[(size_t)BATCH*DIM], g_xm_lo[(size_t)BATCH*DIM];
__device__ float         g_z[(size_t)BATCH*DIM2];
__device__ __nv_bfloat16 g_zn_hi[(size_t)BATCH*DIM2], g_zn_lo[(size_t)BATCH*DIM2];
__device__ __nv_bfloat16 g_wo1_hi[DIM*DIM], g_wo1_lo[DIM*DIM];
__device__ __nv_bfloat16 g_wo2_hi[DIM*DIM], g_wo2_lo[DIM*DIM];
__device__ __nv_bfloat16 g_wv1t_hi[DIM*DIM], g_wv1t_lo[DIM*DIM];
__device__ __nv_bfloat16 g_wv2t_hi[DIM*DIM], g_wv2t_lo[DIM*DIM];
__device__ float         g_B1t[DIM*DIM], g_B2t[DIM*DIM];
__device__ __nv_bfloat16 g_B1_hi[DIM*DIM], g_B1_lo[DIM*DIM];
__device__ __nv_bfloat16 g_B2_hi[DIM*DIM], g_B2_lo[DIM*DIM];
__device__ __nv_bfloat16 g_wp_hi[DIM*DIM2], g_wp_lo[DIM*DIM2];
__device__ float         g_c1[DIM], g_c2[DIM];

// ---------------- low-level helpers (all sm_80-baseline PTX) ----------------
__device__ __forceinline__ uint32_t s2u(const void* p) {
    uint32_t a;
    asm("{ .reg .u64 t; cvta.to.shared.u64 t, %1; cvt.u32.u64 %0, t; }" : "=r"(a) : "l"(p));
    return a;
}
__device__ __forceinline__ void cp16(uint32_t d, const void* s) {
    asm volatile("cp.async.cg.shared.global [%0], [%1], 16;" :: "r"(d), "l"(s));
}
__device__ __forceinline__ void ldm4(uint32_t* r, uint32_t addr) {
    asm volatile("ldmatrix.sync.aligned.m8n8.x4.shared.b16 {%0,%1,%2,%3}, [%4];"
                 : "=r"(r[0]), "=r"(r[1]), "=r"(r[2]), "=r"(r[3]) : "r"(addr));
}
__device__ __forceinline__ void mma16816(float* d, const uint32_t* a, const uint32_t* b) {
    asm volatile(
        "mma.sync.aligned.m16n8k16.row.col.f32.bf16.bf16.f32 "
        "{%0,%1,%2,%3}, {%4,%5,%6,%7}, {%8,%9}, {%0,%1,%2,%3};"
        : "+f"(d[0]), "+f"(d[1]), "+f"(d[2]), "+f"(d[3])
        : "r"(a[0]), "r"(a[1]), "r"(a[2]), "r"(a[3]), "r"(b[0]), "r"(b[1]));
}

// ---------------- mma.sync bf16x3 GEMM ----------------
// C[m,n] = sum_k (Ah+Al)[m,k]*(Bh+Bl)[n,k] (+bias[n], optional exact GELU)
// A: [M,K] row-major bf16 hi/lo.  B: [N,K] row-major bf16 hi/lo.
// CTA tile 256x128x64, 8 warps (4m x 2n), warp tile 64x64. 2-stage cp.async.
#define MT 256
#define NT 128
#define KC 64
#define STRIDE 72                       // smem row pitch in bf16 (144B; ldmatrix conflict-free)
#define A_TILE (MT*STRIDE*2)            // 36864 B
#define B_TILE (NT*STRIDE*2)            // 18432 B
#define STAGE  (2*A_TILE + 2*B_TILE)    // 110592 B
#define SMEM_TOT (2*STAGE)              // 221184 B

template <bool GELU>
__global__ __launch_bounds__(256, 1)
void mma_gemm(const __nv_bfloat16* __restrict__ Ah, const __nv_bfloat16* __restrict__ Al,
              const __nv_bfloat16* __restrict__ Bh, const __nv_bfloat16* __restrict__ Bl,
              float* __restrict__ C, int ldc, const float* __restrict__ bias, int K)
{
    extern __shared__ char smem[];
    const uint32_t base = s2u(smem);
    const int tid  = threadIdx.x;
    const int wid  = tid >> 5;
    const int lane = tid & 31;
    const int m0 = blockIdx.y * MT;
    const int n0 = blockIdx.x * NT;
    const int warp_m0 = (wid & 3) * 64;
    const int warp_n0 = (wid >> 2) * 64;

    float acc[4][8][4];
#pragma unroll
    for (int i = 0; i < 4; i++)
#pragma unroll
        for (int j = 0; j < 8; j++)
#pragma unroll
            for (int q = 0; q < 4; q++) acc[i][j][q] = 0.0f;

    auto load_stage = [&](int s, int k0) {
        const uint32_t stA_h = base + s * STAGE;
        const uint32_t stA_l = stA_h + A_TILE;
        const uint32_t stB_h = stA_h + 2 * A_TILE;
        const uint32_t stB_l = stB_h + B_TILE;
        // A: 256 rows x 8 x 16B segments (hi + lo)
        for (int i = tid; i < MT * 8; i += 256) {
            const int r = i >> 3, seg = i & 7;
            const uint32_t off = (uint32_t)(r * (STRIDE * 2) + seg * 16);
            const size_t gs = (size_t)(m0 + r) * K + k0 + seg * 8;
            cp16(stA_h + off, Ah + gs);
            cp16(stA_l + off, Al + gs);
        }
        // B: 128 rows x 8 segments (hi + lo)
        for (int i = tid; i < NT * 8; i += 256) {
            const int r = i >> 3, seg = i & 7;
            const uint32_t off = (uint32_t)(r * (STRIDE * 2) + seg * 16);
            const size_t gs = (size_t)(n0 + r) * K + k0 + seg * 8;
            cp16(stB_h + off, Bh + gs);
            cp16(stB_l + off, Bl + gs);
        }
        asm volatile("cp.async.commit_group;" ::: "memory");
    };

    const int nk = K / KC;
    load_stage(0, 0);
    load_stage(1, KC);

    // per-lane ldmatrix coordinates
    const int a_row = warp_m0 + (lane & 15);
    const int a_col = (lane >> 4) << 3;
    const int b_row = warp_n0 + (lane & 7) + ((lane >> 4) << 3);
    const int b_col = ((lane >> 3) & 1) << 3;

    for (int i = 0; i < nk; i++) {
        if (i + 1 < nk) asm volatile("cp.async.wait_group 1;" ::: "memory");
        else            asm volatile("cp.async.wait_group 0;" ::: "memory");
        __syncthreads();

        const uint32_t stA_h = base + (i & 1) * STAGE;
        const uint32_t stA_l = stA_h + A_TILE;
        const uint32_t stB_h = stA_h + 2 * A_TILE;
        const uint32_t stB_l = stB_h + B_TILE;

#pragma unroll
        for (int ks = 0; ks < 4; ks++) {
            const int k0 = ks * 16;
            uint32_t ah[4][4], al[4][4], bh[4][4], bl[4][4];
#pragma unroll
            for (int mf = 0; mf < 4; mf++) {
                const uint32_t ao = (uint32_t)((a_row + mf * 16) * STRIDE + k0 + a_col) * 2;
                ldm4(ah[mf], stA_h + ao);
                ldm4(al[mf], stA_l + ao);
            }
#pragma unroll
            for (int bp = 0; bp < 4; bp++) {
                const uint32_t bo = (uint32_t)((b_row + bp * 16) * STRIDE + k0 + b_col) * 2;
                ldm4(bh[bp], stB_h + bo);
                ldm4(bl[bp], stB_l + bo);
            }
#pragma unroll
            for (int mf = 0; mf < 4; mf++) {
#pragma unroll
                for (int bp = 0; bp < 4; bp++) {
                    mma16816(acc[mf][2 * bp + 0], ah[mf], &bh[bp][0]);   // hi*hi
                    mma16816(acc[mf][2 * bp + 1], ah[mf], &bh[bp][2]);
                    mma16816(acc[mf][2 * bp + 0], ah[mf], &bl[bp][0]);   // hi*lo
                    mma16816(acc[mf][2 * bp + 1], ah[mf], &bl[bp][2]);
                    mma16816(acc[mf][2 * bp + 0], al[mf], &bh[bp][0]);   // lo*hi
                    mma16816(acc[mf][2 * bp + 1], al[mf], &bh[bp][2]);
                }
            }
        }

        __syncthreads();
        if (i + 2 < nk) load_stage(i & 1, (i + 2) * KC);
    }

    // ---- epilogue ----
    const int r_base = m0 + warp_m0 + (lane >> 2);
    const int c_base = n0 + warp_n0 + ((lane & 3) << 1);
#pragma unroll
    for (int mf = 0; mf < 4; mf++) {
#pragma unroll
        for (int nf = 0; nf < 8; nf++) {
            const int cc = c_base + nf * 8;
            float b0 = 0.0f, b1 = 0.0f;
            if (bias) { b0 = bias[cc]; b1 = bias[cc + 1]; }
            float v0 = acc[mf][nf][0] + b0;
            float v1 = acc[mf][nf][1] + b1;
            float v2 = acc[mf][nf][2] + b0;
            float v3 = acc[mf][nf][3] + b1;
            if (GELU) {
                v0 = 0.5f * v0 * (1.0f + erff(v0 * 0.70710678118654752f));
                v1 = 0.5f * v1 * (1.0f + erff(v1 * 0.70710678118654752f));
                v2 = 0.5f * v2 * (1.0f + erff(v2 * 0.70710678118654752f));
                v3 = 0.5f * v3 * (1.0f + erff(v3 * 0.70710678118654752f));
            }
            const int row0 = r_base + mf * 16;
            *reinterpret_cast<float2*>(&C[(size_t)row0 * ldc + cc])       = make_float2(v0, v1);
            *reinterpret_cast<float2*>(&C[(size_t)(row0 + 8) * ldc + cc]) = make_float2(v2, v3);
        }
    }
}

// ---------------- split: fp32 -> (hi, lo) bf16 ----------------
__device__ __forceinline__ void split_store4(__nv_bfloat16* __restrict__ oh,
                                             __nv_bfloat16* __restrict__ ol,
                                             size_t idx, float4 v)
{
    __nv_bfloat162 h0, h1, l0, l1;
    h0.x = __float2bfloat16_rn(v.x); h0.y = __float2bfloat16_rn(v.y);
    h1.x = __float2bfloat16_rn(v.z); h1.y = __float2bfloat16_rn(v.w);
    l0.x = __float2bfloat16_rn(v.x - __bfloat162float(h0.x));
    l0.y = __float2bfloat16_rn(v.y - __bfloat162float(h0.y));
    l1.x = __float2bfloat16_rn(v.z - __bfloat162float(h1.x));
    l1.y = __float2bfloat16_rn(v.w - __bfloat162float(h1.y));
    reinterpret_cast<__nv_bfloat162*>(oh + idx)[0] = h0;
    reinterpret_cast<__nv_bfloat162*>(oh + idx)[1] = h1;
    reinterpret_cast<__nv_bfloat162*>(ol + idx)[0] = l0;
    reinterpret_cast<__nv_bfloat162*>(ol + idx)[1] = l1;
}

__global__ void split_kernel(const float* __restrict__ x,
                             __nv_bfloat16* __restrict__ h, __nv_bfloat16* __restrict__ l,
                             int n4)
{
    int i = blockIdx.x * blockDim.x + threadIdx.x;
    if (i < n4) {
        float4 v = reinterpret_cast<const float4*>(x)[i];
        split_store4(h, l, (size_t)i * 4, v);
    }
}

// transpose + split: out[c][r] = in[r][c]
__global__ void tsplit_kernel(const float* __restrict__ in, int R, int Ccols,
                              __nv_bfloat16* __restrict__ h, __nv_bfloat16* __restrict__ l)
{
    __shared__ float t[32][33];
    const int r0 = blockIdx.y * 32, c0 = blockIdx.x * 32;
    const int tx = threadIdx.x, ty = threadIdx.y;  // 32 x 8
#pragma unroll
    for (int i = 0; i < 4; i++)
        t[ty + 8 * i][tx] = in[(size_t)(r0 + ty + 8 * i) * Ccols + c0 + tx];
    __syncthreads();
#pragma unroll
    for (int i = 0; i < 4; i++) {
        const int rr = ty + 8 * i;
        const float v = t[tx][rr];
        const size_t o = (size_t)(c0 + rr) * R + r0 + tx;
        __nv_bfloat16 hh = __float2bfloat16_rn(v);
        h[o] = hh;
        l[o] = __float2bfloat16_rn(v - __bfloat162float(hh));
    }
}

// ---------------- combined bias: c[n] = sum_j wo[n,j]*bv[j] + bo[n] ----------------
__global__ void biasc_kernel(const float* __restrict__ wo, const float* __restrict__ bv,
                             const float* __restrict__ bo, float* __restrict__ c)
{
    __shared__ float red[4];
    const int n = blockIdx.x;
    const int tid = threadIdx.x;  // 128
    float s = 0.0f;
    for (int j = tid; j < DIM; j += 128) s += wo[(size_t)n * DIM + j] * bv[j];
#pragma unroll
    for (int o = 16; o > 0; o >>= 1) s += __shfl_xor_sync(0xFFFFFFFFu, s, o);
    if ((tid & 31) == 0) red[tid >> 5] = s;
    __syncthreads();
    if (tid == 0) c[n] = red[0] + red[1] + red[2] + red[3] + bo[n];
}

// ---------------- LayerNorm(2048) + split to bf16 hi/lo ----------------
__global__ void ln_split_kernel(const float* __restrict__ z,
                                const float* __restrict__ g, const float* __restrict__ b,
                                __nv_bfloat16* __restrict__ oh, __nv_bfloat16* __restrict__ ol)
{
    __shared__ float redS[8], redQ[8];
    const size_t base = (size_t)blockIdx.x * DIM2;
    const int tid = threadIdx.x;  // 256

    float4 v0 = *reinterpret_cast<const float4*>(&z[base + tid * 4]);
    float4 v1 = *reinterpret_cast<const float4*>(&z[base + 1024 + tid * 4]);

    float s = v0.x + v0.y + v0.z + v0.w + v1.x + v1.y + v1.z + v1.w;
    float q = v0.x * v0.x + v0.y * v0.y + v0.z * v0.z + v0.w * v0.w
            + v1.x * v1.x + v1.y * v1.y + v1.z * v1.z + v1.w * v1.w;
#pragma unroll
    for (int o = 16; o > 0; o >>= 1) {
        s += __shfl_xor_sync(0xFFFFFFFFu, s, o);
        q += __shfl_xor_sync(0xFFFFFFFFu, q, o);
    }
    if ((tid & 31) == 0) { redS[tid >> 5] = s; redQ[tid >> 5] = q; }
    __syncthreads();
    float S = 0.0f, Q = 0.0f;
#pragma unroll
    for (int w = 0; w < 8; w++) { S += redS[w]; Q += redQ[w]; }

    const float mu = S * (1.0f / DIM2);
    const float var = Q * (1.0f / DIM2) - mu * mu;
    const float rstd = rsqrtf(var + 1e-5f);

    float4 g0 = *reinterpret_cast<const float4*>(&g[tid * 4]);
    float4 g1 = *reinterpret_cast<const float4*>(&g[1024 + tid * 4]);
    float4 b0 = *reinterpret_cast<const float4*>(&b[tid * 4]);
    float4 b1 = *reinterpret_cast<const float4*>(&b[1024 + tid * 4]);

    v0.x = (v0.x - mu) * rstd * g0.x + b0.x;
    v0.y = (v0.y - mu) * rstd * g0.y + b0.y;
    v0.z = (v0.z - mu) * rstd * g0.z + b0.z;
    v0.w = (v0.w - mu) * rstd * g0.w + b0.w;
    v1.x = (v1.x - mu) * rstd * g1.x + b1.x;
    v1.y = (v1.y - mu) * rstd * g1.y + b1.y;
    v1.z = (v1.z - mu) * rstd * g1.z + b1.z;
    v1.w = (v1.w - mu) * rstd * g1.w + b1.w;

    split_store4(oh, ol, base + tid * 4, v0);
    split_store4(oh, ol, base + 1024 + tid * 4, v1);
}

// ---------------- launch ----------------
extern "C" void kernel_launch(void* const* d_in, const int* in_sizes, int n_in,
                              void* d_out, int out_size)
{
    const float* x_u    = (const float*)d_in[0];
    const float* x_m    = (const float*)d_in[1];
    const float* w_qkv1 = (const float*)d_in[2];
    const float* b_qkv1 = (const float*)d_in[3];
    const float* w_o1   = (const float*)d_in[4];
    const float* b_o1   = (const float*)d_in[5];
    const float* w_qkv2 = (const float*)d_in[6];
    const float* b_qkv2 = (const float*)d_in[7];
    const float* w_o2   = (const float*)d_in[8];
    const float* b_o2   = (const float*)d_in[9];
    const float* ln_g   = (const float*)d_in[10];
    const float* ln_b   = (const float*)d_in[11];
    const float* w_proj = (const float*)d_in[12];
    const float* b_proj = (const float*)d_in[13];
    float* out = (float*)d_out;

    const float* wv1 = w_qkv1 + (size_t)2 * DIM * DIM;
    const float* bv1 = b_qkv1 + 2 * DIM;
    const float* wv2 = w_qkv2 + (size_t)2 * DIM * DIM;
    const float* bv2 = b_qkv2 + 2 * DIM;

    __nv_bfloat16 *xu_h, *xu_l, *xm_h, *xm_l, *zn_h, *zn_l;
    __nv_bfloat16 *wo1_h, *wo1_l, *wo2_h, *wo2_l, *wv1t_h, *wv1t_l, *wv2t_h, *wv2t_l;
    __nv_bfloat16 *B1_h, *B1_l, *B2_h, *B2_l, *wp_h, *wp_l;
    float *z, *B1t, *B2t, *c1, *c2;
    cudaGetSymbolAddress((void**)&xu_h, g_xu_hi);   cudaGetSymbolAddress((void**)&xu_l, g_xu_lo);
    cudaGetSymbolAddress((void**)&xm_h, g_xm_hi);   cudaGetSymbolAddress((void**)&xm_l, g_xm_lo);
    cudaGetSymbolAddress((void**)&z, g_z);
    cudaGetSymbolAddress((void**)&zn_h, g_zn_hi);   cudaGetSymbolAddress((void**)&zn_l, g_zn_lo);
    cudaGetSymbolAddress((void**)&wo1_h, g_wo1_hi); cudaGetSymbolAddress((void**)&wo1_l, g_wo1_lo);
    cudaGetSymbolAddress((void**)&wo2_h, g_wo2_hi); cudaGetSymbolAddress((void**)&wo2_l, g_wo2_lo);
    cudaGetSymbolAddress((void**)&wv1t_h, g_wv1t_hi); cudaGetSymbolAddress((void**)&wv1t_l, g_wv1t_lo);
    cudaGetSymbolAddress((void**)&wv2t_h, g_wv2t_hi); cudaGetSymbolAddress((void**)&wv2t_l, g_wv2t_lo);
    cudaGetSymbolAddress((void**)&B1t, g_B1t);      cudaGetSymbolAddress((void**)&B2t, g_B2t);
    cudaGetSymbolAddress((void**)&B1_h, g_B1_hi);   cudaGetSymbolAddress((void**)&B1_l, g_B1_lo);
    cudaGetSymbolAddress((void**)&B2_h, g_B2_hi);   cudaGetSymbolAddress((void**)&B2_l, g_B2_lo);
    cudaGetSymbolAddress((void**)&wp_h, g_wp_hi);   cudaGetSymbolAddress((void**)&wp_l, g_wp_lo);
    cudaGetSymbolAddress((void**)&c1, g_c1);        cudaGetSymbolAddress((void**)&c2, g_c2);

    cudaFuncSetAttribute(mma_gemm<false>, cudaFuncAttributeMaxDynamicSharedMemorySize, SMEM_TOT);
    cudaFuncSetAttribute(mma_gemm<true>,  cudaFuncAttributeMaxDynamicSharedMemorySize, SMEM_TOT);

    // 1) splits of inputs / weights
    split_kernel<<<(BATCH * DIM / 4) / 256, 256>>>(x_u, xu_h, xu_l, BATCH * DIM / 4);
    split_kernel<<<(BATCH * DIM / 4) / 256, 256>>>(x_m, xm_h, xm_l, BATCH * DIM / 4);
    split_kernel<<<(DIM * DIM / 4) / 256, 256>>>(w_o1, wo1_h, wo1_l, DIM * DIM / 4);
    split_kernel<<<(DIM * DIM / 4) / 256, 256>>>(w_o2, wo2_h, wo2_l, DIM * DIM / 4);
    split_kernel<<<(DIM * DIM2 / 4) / 256, 256>>>(w_proj, wp_h, wp_l, DIM * DIM2 / 4);
    tsplit_kernel<<<dim3(32, 32), dim3(32, 8)>>>(wv1, DIM, DIM, wv1t_h, wv1t_l);
    tsplit_kernel<<<dim3(32, 32), dim3(32, 8)>>>(wv2, DIM, DIM, wv2t_h, wv2t_l);

    // 2) combined biases: c = wo @ bv + bo
    biasc_kernel<<<DIM, 128>>>(w_o1, bv1, b_o1, c1);
    biasc_kernel<<<DIM, 128>>>(w_o2, bv2, b_o2, c2);

    // 3) combined weights: B1t[n,k] = sum_j wo1[n,j]*wv1[j,k]  (A = wo1, B = wv1^T)
    mma_gemm<false><<<dim3(DIM / NT, DIM / MT), 256, SMEM_TOT>>>(
        wo1_h, wo1_l, wv1t_h, wv1t_l, B1t, DIM, nullptr, DIM);
    mma_gemm<false><<<dim3(DIM / NT, DIM / MT), 256, SMEM_TOT>>>(
        wo2_h, wo2_l, wv2t_h, wv2t_l, B2t, DIM, nullptr, DIM);
    split_kernel<<<(DIM * DIM / 4) / 256, 256>>>(B1t, B1_h, B1_l, DIM * DIM / 4);
    split_kernel<<<(DIM * DIM / 4) / 256, 256>>>(B2t, B2_h, B2_l, DIM * DIM / 4);

    // 4) z1 = x_u @ B1^T + c1 -> z[:, :1024] ; z2 = x_m @ B2^T + c2 -> z[:, 1024:]
    mma_gemm<false><<<dim3(DIM / NT, BATCH / MT), 256, SMEM_TOT>>>(
        xu_h, xu_l, B1_h, B1_l, z, DIM2, c1, DIM);
    mma_gemm<false><<<dim3(DIM / NT, BATCH / MT), 256, SMEM_TOT>>>(
        xm_h, xm_l, B2_h, B2_l, z + DIM, DIM2, c2, DIM);

    // 5) LayerNorm + split
    ln_split_kernel<<<BATCH, 256>>>(z, ln_g, ln_b, zn_h, zn_l);

    // 6) out = GELU(zn @ w_proj^T + b_proj)   (w_proj is [N=1024, K=2048] row-major)
    mma_gemm<true><<<dim3(DIM / NT, BATCH / MT), 256, SMEM_TOT>>>(
        zn_h, zn_l, wp_h, wp_l, out, DIM, b_proj, DIM2);
}